// round 5
// baseline (speedup 1.0000x reference)
#include <cuda_runtime.h>

// ---------------------------------------------------------------------------
// QualityAwarePrompt — GB300 (sm_103a)
//
// Inputs (metadata order):
//  0: x_embed  (B,64,512) f32  -- values unused (only dtype matters)
//  1: quality  (B,1)      f32
//  2: keys     (20,512)   f32
//  3: pe       (20,64,512)f32
//  4: w1 (1,256)  5: b1 (256)  6: ln_g (256)  7: ln_b (256)
//  8: w2 (256,512)  9: b2 (512)
// Output: (B,64,512) f32
//
// Kernel 1 (qap_select): per 8-batch block, computes query = relu(LN(q*w1+b1)) @ w2 + b2
//   (LN stats analytic in scalar q), cosine sims vs 20 keys, softmax, top-5,
//   per-batch length; packs 12 floats/batch into g_pack.
//   Matvec uses packed fma.rn.f32x2 (2 flops/inst).
// Kernel 2 (qap_blend): per (l, 64-batch chunk) block, stages 20x512 f32 slice
//   of prompt_embeddings in smem, blends top-5 per batch, masks by length,
//   streaming-stores 128 MiB output.
// ---------------------------------------------------------------------------

#define NPOOL 20
#define LMAX  64
#define DD    512
#define HH    256

__device__ float g_pack[4096 * 12];   // [w0..w4, idx0..idx4 (bitcast), len (bitcast), pad]

// ---- f32x2 packed-math helpers (sm_100+) ----------------------------------
__device__ __forceinline__ unsigned long long pk2(float lo, float hi) {
    unsigned long long r;
    asm("mov.b64 %0, {%1, %2};" : "=l"(r) : "f"(lo), "f"(hi));
    return r;
}
__device__ __forceinline__ void upk2(unsigned long long v, float& lo, float& hi) {
    asm("mov.b64 {%0, %1}, %2;" : "=f"(lo), "=f"(hi) : "l"(v));
}
__device__ __forceinline__ unsigned long long ffma2(unsigned long long a,
                                                    unsigned long long b,
                                                    unsigned long long c) {
    unsigned long long d;
    asm("fma.rn.f32x2 %0, %1, %2, %3;" : "=l"(d) : "l"(a), "l"(b), "l"(c));
    return d;
}

// ---- block-wide sum for 128-thread blocks ---------------------------------
__device__ __forceinline__ float block_sum_128(float v, float* scr) {
    #pragma unroll
    for (int o = 16; o; o >>= 1) v += __shfl_down_sync(0xffffffffu, v, o);
    __syncthreads();                      // protect scr against previous use
    if ((threadIdx.x & 31) == 0) scr[threadIdx.x >> 5] = v;
    __syncthreads();
    return scr[0] + scr[1] + scr[2] + scr[3];
}

// ===========================================================================
// Kernel 1: selection (grid = B/8 blocks, 128 threads)
// ===========================================================================
__global__ __launch_bounds__(128)
void qap_select(const float* __restrict__ quality,
                const float* __restrict__ keys,
                const float* __restrict__ w1,
                const float* __restrict__ b1,
                const float* __restrict__ lng,
                const float* __restrict__ lnb,
                const float* __restrict__ w2,
                const float* __restrict__ b2,
                int B)
{
    // sh: phase A/B = duplicated-h buffer [8 batches][256 j][2 dup] = 4096 f
    //     phase C   = queries            [8 batches][512 d]        = 4096 f
    __shared__ __align__(16) float sh[8 * DD];
    __shared__ float s_red[4];
    __shared__ float s_kinv[NPOOL];
    __shared__ float s_qinv[8];
    __shared__ float s_sims[8 * NPOOL];

    const int tid  = threadIdx.x;
    const int lane = tid & 31;
    const int wrp  = tid >> 5;
    const int b0   = blockIdx.x * 8;

    // ---- global quality mean -> softmax scale -----------------------------
    float qs = 0.f;
    for (int i = tid; i < B; i += 128) qs += quality[i];
    qs = block_sum_128(qs, s_red);
    const float scale = 1.0f + 0.5f * (qs / (float)B);

    // ---- analytic LN stats of h(q) = q*w1 + b1 ----------------------------
    float sw = 0.f, sb = 0.f, sww = 0.f, swb = 0.f, sbb = 0.f;
    for (int j = tid; j < HH; j += 128) {
        float a = w1[j], c = b1[j];
        sw += a; sb += c; sww += a * a; swb += a * c; sbb += c * c;
    }
    sw  = block_sum_128(sw,  s_red);
    sb  = block_sum_128(sb,  s_red);
    sww = block_sum_128(sww, s_red);
    swb = block_sum_128(swb, s_red);
    sbb = block_sum_128(sbb, s_red);
    const float ih = 1.0f / (float)HH;
    const float mw = sw * ih, mb = sb * ih;
    const float Av = sww * ih - mw * mw;
    const float Bv = swb * ih - mw * mb;
    const float Cv = sbb * ih - mb * mb;

    // ---- key inverse norms (warp per rows) --------------------------------
    for (int p = wrp; p < NPOOL; p += 4) {
        float s = 0.f;
        #pragma unroll
        for (int i = 0; i < DD / 32; ++i) {
            float v = keys[p * DD + lane + 32 * i];
            s += v * v;
        }
        #pragma unroll
        for (int o = 16; o; o >>= 1) s += __shfl_down_sync(0xffffffffu, s, o);
        if (lane == 0) s_kinv[p] = 1.0f / fmaxf(sqrtf(s), 1e-8f);
    }

    // ---- phase A: h = relu(LN(q*w1+b1)), stored DUPLICATED as f32 pairs ---
    #pragma unroll
    for (int e = 0; e < 16; ++e) {
        int idx = tid + e * 128;          // 0..2047
        int bb = idx >> 8, j = idx & 255;
        float q   = quality[b0 + bb];
        float var = fmaf(q, fmaf(q, Av, 2.0f * Bv), Cv) + 1e-5f;
        float r   = rsqrtf(var);
        r = r * (1.5f - 0.5f * var * r * r);   // Newton refine
        float h = (q * (w1[j] - mw) + (b1[j] - mb)) * r * lng[j] + lnb[j];
        h = fmaxf(h, 0.0f);
        sh[bb * DD + 2 * j]     = h;
        sh[bb * DD + 2 * j + 1] = h;
    }
    __syncthreads();

    // ---- phase B: query = h @ w2 + b2, packed f32x2 FMA -------------------
    const ulonglong2* __restrict__ w2u = (const ulonglong2*)w2;
    const ulonglong2* shu = (const ulonglong2*)sh;   // shu[bb*128 + j2]
    const int d4 = tid;                               // 0..127 -> 4 d-values
    float4 bias = ((const float4*)b2)[d4];
    unsigned long long acc0[8], acc1[8];
    #pragma unroll
    for (int bb = 0; bb < 8; ++bb) {
        acc0[bb] = pk2(bias.x, bias.y);
        acc1[bb] = pk2(bias.z, bias.w);
    }
    #pragma unroll 4
    for (int j2 = 0; j2 < HH / 2; ++j2) {            // covers j = 2*j2, 2*j2+1
        ulonglong2 wA = w2u[(2 * j2)     * 128 + d4];
        ulonglong2 wB = w2u[(2 * j2 + 1) * 128 + d4];
        #pragma unroll
        for (int bb = 0; bb < 8; ++bb) {
            ulonglong2 hp = shu[bb * 128 + j2];      // (h_j dup, h_{j+1} dup)
            acc0[bb] = ffma2(wA.x, hp.x, acc0[bb]);
            acc1[bb] = ffma2(wA.y, hp.x, acc1[bb]);
            acc0[bb] = ffma2(wB.x, hp.y, acc0[bb]);
            acc1[bb] = ffma2(wB.y, hp.y, acc1[bb]);
        }
    }
    __syncthreads();   // everyone done reading sh before overwrite

    // ---- write queries into sh ---------------------------------------------
    #pragma unroll
    for (int bb = 0; bb < 8; ++bb) {
        float x0, x1, x2, x3;
        upk2(acc0[bb], x0, x1);
        upk2(acc1[bb], x2, x3);
        ((float4*)sh)[bb * 128 + d4] = make_float4(x0, x1, x2, x3);
    }
    __syncthreads();

    // ---- query inverse norms ----------------------------------------------
    for (int bb = wrp; bb < 8; bb += 4) {
        float s = 0.f;
        #pragma unroll
        for (int i = 0; i < DD / 32; ++i) {
            float v = sh[bb * DD + lane + 32 * i];
            s += v * v;
        }
        #pragma unroll
        for (int o = 16; o; o >>= 1) s += __shfl_down_sync(0xffffffffu, s, o);
        if (lane == 0) s_qinv[bb] = 1.0f / fmaxf(sqrtf(s), 1e-8f);
    }
    __syncthreads();

    // ---- cosine sims: 8 batches x 20 keys ---------------------------------
    for (int id = wrp; id < 8 * NPOOL; id += 4) {
        int bb = id / NPOOL, p = id % NPOOL;
        float s = 0.f;
        #pragma unroll
        for (int i = 0; i < DD / 32; ++i)
            s += sh[bb * DD + lane + 32 * i] * keys[p * DD + lane + 32 * i];
        #pragma unroll
        for (int o = 16; o; o >>= 1) s += __shfl_down_sync(0xffffffffu, s, o);
        if (lane == 0) s_sims[id] = s * s_qinv[bb] * s_kinv[p];
    }
    __syncthreads();

    // ---- softmax + top-5 + length, packed output --------------------------
    if (tid < 8) {
        int bb = tid, b = b0 + bb;
        float z[NPOOL], e[NPOOL];
        float m = -1e30f;
        #pragma unroll
        for (int p = 0; p < NPOOL; ++p) {
            z[p] = s_sims[bb * NPOOL + p] * scale;
            m = fmaxf(m, z[p]);
        }
        float sum = 0.f;
        #pragma unroll
        for (int p = 0; p < NPOOL; ++p) { e[p] = expf(z[p] - m); sum += e[p]; }
        float inv = 1.0f / sum;

        float wk[5]; int ik[5];
        unsigned int used = 0;
        #pragma unroll
        for (int k = 0; k < 5; ++k) {
            float bv = -1e30f; int bi = 0;
            #pragma unroll
            for (int p = 0; p < NPOOL; ++p) {
                bool ok = !((used >> p) & 1u) && (z[p] > bv);
                if (ok) { bv = z[p]; bi = p; }
            }
            used |= (1u << bi);
            wk[k] = e[bi] * inv;
            ik[k] = bi;
        }

        float q  = quality[b];
        float lf = truncf(5.0f + 59.0f * (1.0f - q / 5.0f));
        int   L  = (int)lf;
        L = min(max(L, 5), 64);

        float* pk = &g_pack[b * 12];
        pk[0] = wk[0]; pk[1] = wk[1]; pk[2] = wk[2]; pk[3] = wk[3]; pk[4] = wk[4];
        pk[5] = __int_as_float(ik[0]);
        pk[6] = __int_as_float(ik[1]);
        pk[7] = __int_as_float(ik[2]);
        pk[8] = __int_as_float(ik[3]);
        pk[9] = __int_as_float(ik[4]);
        pk[10] = __int_as_float(L);
        pk[11] = 0.0f;
    }
}

// ===========================================================================
// Kernel 2: blend (grid = (64, B/64), 256 threads)
//   block = one sequence position l, chunk of 64 batches
// ===========================================================================
__global__ __launch_bounds__(256)
void qap_blend(const float4* __restrict__ pe4, float4* __restrict__ out4)
{
    __shared__ __align__(16) float4 tile[NPOOL * 128];  // 40 KiB: 20 prompts x 512 f
    __shared__ float4 meta[64 * 3];                     //  3 KiB: 64 batches x 12 f

    const int tid = threadIdx.x;
    const int l   = blockIdx.x;
    const int b0  = blockIdx.y * 64;

    // stage PE[:, l, :] slice
    for (int i = tid; i < NPOOL * 128; i += 256) {
        int p = i >> 7, c = i & 127;
        tile[i] = pe4[(p * LMAX + l) * 128 + c];
    }
    // stage per-batch metadata
    const float4* packv = (const float4*)g_pack;
    for (int i = tid; i < 64 * 3; i += 256) meta[i] = packv[b0 * 3 + i];
    __syncthreads();

    const int sub = tid >> 7;     // 0/1 -> 2 batches per iteration
    const int d4  = tid & 127;    // float4 column

    #pragma unroll 2
    for (int it = 0; it < 32; ++it) {
        int bb = it * 2 + sub;
        float4 m0 = meta[bb * 3 + 0];   // w0..w3
        float4 m1 = meta[bb * 3 + 1];   // w4, idx0, idx1, idx2
        float4 m2 = meta[bb * 3 + 2];   // idx3, idx4, len, pad
        float4 r  = make_float4(0.f, 0.f, 0.f, 0.f);
        int L = __float_as_int(m2.z);
        if (l < L) {
            float4 v0 = tile[__float_as_int(m1.y) * 128 + d4];
            float4 v1 = tile[__float_as_int(m1.z) * 128 + d4];
            float4 v2 = tile[__float_as_int(m1.w) * 128 + d4];
            float4 v3 = tile[__float_as_int(m2.x) * 128 + d4];
            float4 v4 = tile[__float_as_int(m2.y) * 128 + d4];
            r.x = fmaf(m0.x, v0.x, fmaf(m0.y, v1.x, fmaf(m0.z, v2.x, fmaf(m0.w, v3.x, m1.x * v4.x))));
            r.y = fmaf(m0.x, v0.y, fmaf(m0.y, v1.y, fmaf(m0.z, v2.y, fmaf(m0.w, v3.y, m1.x * v4.y))));
            r.z = fmaf(m0.x, v0.z, fmaf(m0.y, v1.z, fmaf(m0.z, v2.z, fmaf(m0.w, v3.z, m1.x * v4.z))));
            r.w = fmaf(m0.x, v0.w, fmaf(m0.y, v1.w, fmaf(m0.z, v2.w, fmaf(m0.w, v3.w, m1.x * v4.w))));
        }
        // streaming store: don't let 128 MiB of output evict the PE slices in L2
        __stcs(&out4[((b0 + bb) * LMAX + l) * 128 + d4], r);
    }
}

// ===========================================================================
extern "C" void kernel_launch(void* const* d_in, const int* in_sizes, int n_in,
                              void* d_out, int out_size)
{
    (void)n_in; (void)out_size;
    // d_in[0] = x_embed (unused)
    const float* quality = (const float*)d_in[1];
    const float* keys    = (const float*)d_in[2];
    const float* pe      = (const float*)d_in[3];
    const float* w1      = (const float*)d_in[4];
    const float* b1      = (const float*)d_in[5];
    const float* lng     = (const float*)d_in[6];
    const float* lnb     = (const float*)d_in[7];
    const float* w2      = (const float*)d_in[8];
    const float* b2      = (const float*)d_in[9];

    const int B = in_sizes[1];   // quality_score element count = B

    qap_select<<<B / 8, 128>>>(quality, keys, w1, b1, lng, lnb, w2, b2, B);
    qap_blend<<<dim3(LMAX, B / 64), 256>>>((const float4*)pe, (float4*)d_out);
}

// round 6
// speedup vs baseline: 1.2078x; 1.2078x over previous
#include <cuda_runtime.h>

// ---------------------------------------------------------------------------
// QualityAwarePrompt — GB300 (sm_103a)   Round 5
//
// Kernel 1 (qap_select, 256 thr, B/8 blocks):
//   query = relu(LN(q*w1+b1)) @ w2 + b2 with LN stats analytic in scalar q.
//   Low register pressure: each thread owns ONE f32-pair of the query
//   (8 u64 accumulators), w2 read once per block via LDG.64.
//   Emits per-batch DENSE duplicated weight table: 20 x pk2(w,w) u64
//   (top-5 softmax weights scattered, zeros elsewhere) + length.
// Kernel 2 (qap_blend, 256 thr, 32 x B/64 blocks):
//   Each thread caches its (l, float4-col) slice of ALL 20 prompts in
//   registers (packed f32x2). Per batch: 10 LDS.128 broadcast weight loads
//   + 40 fma.rn.f32x2. No tile LDS at all -> FFMA2-pipe bound, stores
//   streamed with __stcs.
// ---------------------------------------------------------------------------

#define NPOOL 20
#define LMAX  64
#define DD    512
#define HH    256

// per batch: 20 u64 duplicated weights, [20].lo = length (int), 21..23 pad
__device__ __align__(16) unsigned long long g_meta[4096 * 24];

// ---- f32x2 packed-math helpers (sm_100+) ----------------------------------
__device__ __forceinline__ unsigned long long pk2(float lo, float hi) {
    unsigned long long r;
    asm("mov.b64 %0, {%1, %2};" : "=l"(r) : "f"(lo), "f"(hi));
    return r;
}
__device__ __forceinline__ void upk2(unsigned long long v, float& lo, float& hi) {
    asm("mov.b64 {%0, %1}, %2;" : "=f"(lo), "=f"(hi) : "l"(v));
}
__device__ __forceinline__ unsigned long long ffma2(unsigned long long a,
                                                    unsigned long long b,
                                                    unsigned long long c) {
    unsigned long long d;
    asm("fma.rn.f32x2 %0, %1, %2, %3;" : "=l"(d) : "l"(a), "l"(b), "l"(c));
    return d;
}

// ---- block-wide sum for 256-thread blocks ---------------------------------
__device__ __forceinline__ float block_sum_256(float v, float* scr) {
    #pragma unroll
    for (int o = 16; o; o >>= 1) v += __shfl_down_sync(0xffffffffu, v, o);
    __syncthreads();
    if ((threadIdx.x & 31) == 0) scr[threadIdx.x >> 5] = v;
    __syncthreads();
    float s = 0.f;
    #pragma unroll
    for (int i = 0; i < 8; ++i) s += scr[i];
    return s;
}

// ===========================================================================
// Kernel 1: selection (grid = B/8, 256 threads)
// ===========================================================================
__global__ __launch_bounds__(256)
void qap_select(const float* __restrict__ quality,
                const float* __restrict__ keys,
                const float* __restrict__ w1,
                const float* __restrict__ b1,
                const float* __restrict__ lng,
                const float* __restrict__ lnb,
                const float* __restrict__ w2,
                const float* __restrict__ b2,
                int B)
{
    // sh: phase A = duplicated-h [8 bb][256 j][2 dup]; phase C = queries [8 bb][512 d]
    __shared__ __align__(16) float sh[8 * DD];
    __shared__ float s_red[8];
    __shared__ float s_kinv[NPOOL];
    __shared__ float s_qinv[8];
    __shared__ float s_sims[8 * NPOOL];

    const int tid  = threadIdx.x;       // 0..255  (== j index, == d-pair index)
    const int lane = tid & 31;
    const int wrp  = tid >> 5;          // 0..7
    const int b0   = blockIdx.x * 8;

    // ---- global quality mean -> softmax scale -----------------------------
    float qs = 0.f;
    for (int i = tid; i < B; i += 256) qs += quality[i];
    qs = block_sum_256(qs, s_red);
    const float scale = 1.0f + 0.5f * (qs / (float)B);

    // ---- analytic LN stats of h(q) = q*w1 + b1 (one j per thread) ---------
    const float a1 = w1[tid], c1 = b1[tid];
    const float sw  = block_sum_256(a1,      s_red);
    const float sb  = block_sum_256(c1,      s_red);
    const float sww = block_sum_256(a1 * a1, s_red);
    const float swb = block_sum_256(a1 * c1, s_red);
    const float sbb = block_sum_256(c1 * c1, s_red);
    const float ih = 1.0f / (float)HH;
    const float mw = sw * ih, mb = sb * ih;
    const float Av = sww * ih - mw * mw;
    const float Bv = swb * ih - mw * mb;
    const float Cv = sbb * ih - mb * mb;

    // ---- key inverse norms ------------------------------------------------
    for (int p = wrp; p < NPOOL; p += 8) {
        float s = 0.f;
        #pragma unroll
        for (int i = 0; i < DD / 32; ++i) {
            float v = keys[p * DD + lane + 32 * i];
            s += v * v;
        }
        #pragma unroll
        for (int o = 16; o; o >>= 1) s += __shfl_down_sync(0xffffffffu, s, o);
        if (lane == 0) s_kinv[p] = 1.0f / fmaxf(sqrtf(s), 1e-8f);
    }

    // ---- phase A: h = relu(LN(q*w1+b1)), stored DUPLICATED ----------------
    {
        const float g = lng[tid], bt = lnb[tid];
        const float aw = a1 - mw, cb = c1 - mb;
        #pragma unroll
        for (int bb = 0; bb < 8; ++bb) {
            float q   = quality[b0 + bb];
            float var = fmaf(q, fmaf(q, Av, 2.0f * Bv), Cv) + 1e-5f;
            float r   = rsqrtf(var);
            r = r * (1.5f - 0.5f * var * r * r);     // Newton refine
            float h = fmaxf(fmaf(q, aw, cb) * r * g + bt, 0.0f);
            sh[bb * DD + 2 * tid]     = h;
            sh[bb * DD + 2 * tid + 1] = h;
        }
    }
    __syncthreads();

    // ---- phase B: query = h @ w2 + b2 (thread owns one f32-pair) ----------
    const unsigned long long* __restrict__ w2u = (const unsigned long long*)w2;
    const unsigned long long* hu = (const unsigned long long*)sh;   // [bb*256 + j]
    float2 bias = ((const float2*)b2)[tid];
    unsigned long long acc[8];
    #pragma unroll
    for (int bb = 0; bb < 8; ++bb) acc[bb] = pk2(bias.x, bias.y);

    #pragma unroll 4
    for (int j = 0; j < HH; ++j) {
        unsigned long long wv = w2u[j * 256 + tid];
        #pragma unroll
        for (int bb = 0; bb < 8; ++bb)
            acc[bb] = ffma2(wv, hu[bb * 256 + j], acc[bb]);
    }
    __syncthreads();    // done reading h before overwrite

    #pragma unroll
    for (int bb = 0; bb < 8; ++bb) {
        float x0, x1;
        upk2(acc[bb], x0, x1);
        ((float2*)sh)[bb * 256 + tid] = make_float2(x0, x1);
    }
    __syncthreads();

    // ---- query inverse norms (one warp per batch) -------------------------
    {
        const int bb = wrp;
        float s = 0.f;
        #pragma unroll
        for (int i = 0; i < DD / 32; ++i) {
            float v = sh[bb * DD + lane + 32 * i];
            s += v * v;
        }
        #pragma unroll
        for (int o = 16; o; o >>= 1) s += __shfl_down_sync(0xffffffffu, s, o);
        if (lane == 0) s_qinv[bb] = 1.0f / fmaxf(sqrtf(s), 1e-8f);
    }
    __syncthreads();

    // ---- cosine sims: 8 x 20 ----------------------------------------------
    for (int id = wrp; id < 8 * NPOOL; id += 8) {
        int bb = id / NPOOL, p = id % NPOOL;
        float s = 0.f;
        #pragma unroll
        for (int i = 0; i < DD / 32; ++i)
            s += sh[bb * DD + lane + 32 * i] * keys[p * DD + lane + 32 * i];
        #pragma unroll
        for (int o = 16; o; o >>= 1) s += __shfl_down_sync(0xffffffffu, s, o);
        if (lane == 0) s_sims[id] = s * s_qinv[bb] * s_kinv[p];
    }
    __syncthreads();

    // ---- softmax + top-5 + length, DENSE duplicated weight table ----------
    if (tid < 8) {
        int bb = tid, b = b0 + bb;
        float z[NPOOL], e[NPOOL];
        float m = -1e30f;
        #pragma unroll
        for (int p = 0; p < NPOOL; ++p) {
            z[p] = s_sims[bb * NPOOL + p] * scale;
            m = fmaxf(m, z[p]);
        }
        float sum = 0.f;
        #pragma unroll
        for (int p = 0; p < NPOOL; ++p) { e[p] = expf(z[p] - m); sum += e[p]; }
        float inv = 1.0f / sum;

        float wk[5]; int ik[5];
        unsigned int used = 0;
        #pragma unroll
        for (int k = 0; k < 5; ++k) {        // lax.top_k: ties keep lowest idx
            float bv = -1e30f; int bi = 0;
            #pragma unroll
            for (int p = 0; p < NPOOL; ++p) {
                bool ok = !((used >> p) & 1u) && (z[p] > bv);
                if (ok) { bv = z[p]; bi = p; }
            }
            used |= (1u << bi);
            wk[k] = e[bi] * inv;
            ik[k] = bi;
        }

        float q  = quality[b];
        float lf = truncf(5.0f + 59.0f * (1.0f - q / 5.0f));
        int   L  = min(max((int)lf, 5), 64);

        unsigned long long* mt = &g_meta[(size_t)b * 24];
        #pragma unroll
        for (int p = 0; p < NPOOL; ++p) {
            float w = 0.f;
            #pragma unroll
            for (int k = 0; k < 5; ++k) w = (ik[k] == p) ? wk[k] : w;
            mt[p] = pk2(w, w);
        }
        mt[20] = (unsigned long long)(unsigned int)L;
        mt[21] = 0ull; mt[22] = 0ull; mt[23] = 0ull;
    }
}

// ===========================================================================
// Kernel 2: blend (grid = (32, B/64), 256 threads)
//   block = two l positions x 128 float4-cols, 64 batches
//   tile held in REGISTERS (20 prompts x 1 float4, packed f32x2) -> dense
//   20-term blend, no tile LDS.
// ===========================================================================
__global__ __launch_bounds__(256, 2)
void qap_blend(const float4* __restrict__ pe4, float4* __restrict__ out4)
{
    __shared__ __align__(16) unsigned long long smeta[64 * 24];   // 12 KiB

    const int tid = threadIdx.x;
    const int l   = blockIdx.x * 2 + (tid >> 7);   // warp-uniform
    const int c   = tid & 127;                     // float4 column
    const int b0  = blockIdx.y * 64;

    // stage meta (64 batches x 24 u64)
    {
        const ulonglong2* gm2 = (const ulonglong2*)&g_meta[(size_t)b0 * 24];
        ulonglong2* sm2 = (ulonglong2*)smeta;
        #pragma unroll
        for (int i = 0; i < 3; ++i) sm2[tid + i * 256] = gm2[tid + i * 256];
    }

    // cache all 20 prompts' float4 for (l, c) in registers, packed f32x2
    unsigned long long ax[NPOOL], ay[NPOOL];
    #pragma unroll
    for (int p = 0; p < NPOOL; ++p) {
        float4 f = pe4[(p * LMAX + l) * 128 + c];
        ax[p] = pk2(f.x, f.y);
        ay[p] = pk2(f.z, f.w);
    }
    __syncthreads();

    float4* outp = out4 + ((size_t)b0 * LMAX + l) * 128 + c;

    #pragma unroll 2
    for (int bb = 0; bb < 64; ++bb) {
        const ulonglong2* mb = (const ulonglong2*)&smeta[bb * 24];
        const int L = *(const int*)&smeta[bb * 24 + 20];   // LDS.32 broadcast
        unsigned long long a0 = 0ull, a1 = 0ull;
        if (l < L) {                                        // warp-uniform branch
            #pragma unroll
            for (int pp = 0; pp < NPOOL / 2; ++pp) {
                ulonglong2 w = mb[pp];                      // LDS.128 broadcast
                a0 = ffma2(w.x, ax[2 * pp],     a0);
                a1 = ffma2(w.x, ay[2 * pp],     a1);
                a0 = ffma2(w.y, ax[2 * pp + 1], a0);
                a1 = ffma2(w.y, ay[2 * pp + 1], a1);
            }
        }
        float4 r;
        upk2(a0, r.x, r.y);
        upk2(a1, r.z, r.w);
        __stcs(&outp[(size_t)bb * LMAX * 128], r);          // streaming store
    }
}

// ===========================================================================
extern "C" void kernel_launch(void* const* d_in, const int* in_sizes, int n_in,
                              void* d_out, int out_size)
{
    (void)n_in; (void)out_size;
    // d_in[0] = x_embed (unused)
    const float* quality = (const float*)d_in[1];
    const float* keys    = (const float*)d_in[2];
    const float* pe      = (const float*)d_in[3];
    const float* w1      = (const float*)d_in[4];
    const float* b1      = (const float*)d_in[5];
    const float* lng     = (const float*)d_in[6];
    const float* lnb     = (const float*)d_in[7];
    const float* w2      = (const float*)d_in[8];
    const float* b2      = (const float*)d_in[9];

    const int B = in_sizes[1];   // quality_score element count = B

    qap_select<<<B / 8, 256>>>(quality, keys, w1, b1, lng, lnb, w2, b2, B);
    qap_blend<<<dim3(LMAX / 2, B / 64), 256>>>((const float4*)pe, (float4*)d_out);
}